// round 5
// baseline (speedup 1.0000x reference)
#include <cuda_runtime.h>

// RoiPooling: fmap [1,128,128,256] f32 NHWC, roi_edges [R,4] f32
// out [R,7,7,256] f32. Adaptive max pool, reference _bin_size semantics.
//
// Fully Lw-specialized: Lw in [7,32] maps bijectively to (mw, wl) via
// mw=(Lw-1)/6, wl=Lw-6*mw. Each template variant has exact compile-time
// loads (immediate offsets, no inner-loop ALU, no wasted loads).
// Column-split: ty=0 handles bins [0,JS), ty=1 bins [JS,7) (JS balances
// load counts) -> no smem reduction, no syncthreads, no idle half.

#define H_DIM 128
#define W_DIM 128
#define C_VEC 64          // 256 channels / 4 (float4)
#define OUT_H 7
#define OUT_W 7
#define ROW_STRIDE ((size_t)W_DIM * C_VEC)   // float4 elems per fmap row

__device__ __forceinline__ int bin_size(int L) {
    int xup = (L + OUT_H - 1) / OUT_H;            // ceil(L/7)
    int m = (xup * (OUT_H - 1) >= L) ? (xup - 1) : xup;
    return m > 1 ? m : 1;
}

__device__ __forceinline__ void fold(float4& a, const float4 v) {
    a.x = fmaxf(a.x, v.x);
    a.y = fmaxf(a.y, v.y);
    a.z = fmaxf(a.z, v.z);
    a.w = fmaxf(a.w, v.w);
}

template<int LW, bool FIRST>
__device__ __forceinline__ void run_half(const float4* __restrict__ fp,
                                         int cnt,
                                         float4* __restrict__ obase)
{
    constexpr int MW  = (LW - 1) / 6;     // bin width (bins 0..5)
    constexpr int WL  = LW - 6 * MW;      // last-bin width, 1..6
    constexpr int JSR = (LW / 2 + MW / 2) / MW;
    constexpr int JS  = JSR < 1 ? 1 : (JSR > 6 ? 6 : JSR);
    constexpr int J0  = FIRST ? 0 : JS;
    constexpr int J1  = FIRST ? JS : OUT_W;
    constexpr int NB  = J1 - J0;

    const float NEG = __int_as_float(0xff800000);   // -inf
    float4 acc[NB];
#pragma unroll
    for (int j = 0; j < NB; ++j)
        acc[j] = make_float4(NEG, NEG, NEG, NEG);

    for (int y = 0; y < cnt; ++y) {
        const float4* row = fp;
        fp += ROW_STRIDE;
#pragma unroll
        for (int j = J0; j < J1; ++j) {
#pragma unroll
            for (int k = 0; k < ((j == OUT_W - 1) ? WL : MW); ++k) {
                fold(acc[j - J0], __ldg(row + (j * MW + k) * C_VEC));
            }
        }
    }

#pragma unroll
    for (int j = J0; j < J1; ++j)
        obase[(size_t)j * C_VEC] = acc[j - J0];
}

__global__ __launch_bounds__(128, 8)
void roi_pool_kernel(const float4* __restrict__ fmap,   // [128,128,64] float4
                     const float4* __restrict__ rois,   // [R] (l,r,t,b)
                     float4* __restrict__ out)          // [R,7,7,64] float4
{
    const int r   = blockIdx.x;       // ROI index
    const int i   = blockIdx.y;       // output row 0..6
    const int tid = threadIdx.x;      // 0..63 channel-group
    const bool first = (threadIdx.y == 0);

    const float4 e = rois[r];
    const int l  = __float2int_rn(128.0f * e.x);
    const int rr = __float2int_rn(128.0f * e.y);
    const int t  = __float2int_rn(128.0f * e.z);
    const int b  = __float2int_rn(128.0f * e.w);

    int Lh = b - t; Lh = Lh < OUT_H ? OUT_H : (Lh > 32 ? 32 : Lh);
    int Lw = rr - l; Lw = Lw < OUT_W ? OUT_W : (Lw > 32 ? 32 : Lw);

    const int mh = bin_size(Lh);

    const int y0 = i * mh;
    int y1 = (i == OUT_H - 1) ? Lh : (i + 1) * mh;
    if (y1 > Lh) y1 = Lh;
    const int cnt = y1 - y0;                       // 1..6

    const float4* fp = fmap + ((size_t)(t + y0) * W_DIM + l) * C_VEC + tid;
    float4* obase = out + ((size_t)r * OUT_H + i) * OUT_W * C_VEC + tid;

#define LW_CASE(LWV) \
    case LWV: \
        if (first) run_half<LWV, true >(fp, cnt, obase); \
        else       run_half<LWV, false>(fp, cnt, obase); \
        break;

    switch (Lw) {
        LW_CASE(7)  LW_CASE(8)  LW_CASE(9)  LW_CASE(10) LW_CASE(11)
        LW_CASE(12) LW_CASE(13) LW_CASE(14) LW_CASE(15) LW_CASE(16)
        LW_CASE(17) LW_CASE(18) LW_CASE(19) LW_CASE(20) LW_CASE(21)
        LW_CASE(22) LW_CASE(23) LW_CASE(24) LW_CASE(25) LW_CASE(26)
        LW_CASE(27) LW_CASE(28) LW_CASE(29) LW_CASE(30) LW_CASE(31)
        default:
            if (first) run_half<32, true >(fp, cnt, obase);
            else       run_half<32, false>(fp, cnt, obase);
            break;
    }
#undef LW_CASE
}

extern "C" void kernel_launch(void* const* d_in, const int* in_sizes, int n_in,
                              void* d_out, int out_size)
{
    const float4* fmap = (const float4*)d_in[0];   // [1,128,128,256] f32
    const float4* rois = (const float4*)d_in[1];   // [R,4] f32
    float4* out = (float4*)d_out;

    const int R = in_sizes[1] / 4;

    dim3 grid(R, OUT_H);
    dim3 block(C_VEC, 2);
    roi_pool_kernel<<<grid, block>>>(fmap, rois, out);
}

// round 7
// speedup vs baseline: 1.1978x; 1.1978x over previous
#include <cuda_runtime.h>

// RoiPooling: fmap [1,128,128,256] f32 NHWC, roi_edges [R,4] f32
// out [R,7,7,256] f32. Adaptive max pool, reference _bin_size semantics.
//
// mw-specialized (5 variants only — I$-friendly), column-split across
// threadIdx.y (ty=0: bins [0,JS), ty=1: bins [JS,7)) -> no smem reduce,
// no syncthreads, no idle half. Tail bin uses predicated loads (no
// wasted L1/L2 wavefronts).

#define H_DIM 128
#define W_DIM 128
#define C_VEC 64          // 256 channels / 4 (float4)
#define OUT_H 7
#define OUT_W 7
#define ROW_STRIDE ((size_t)W_DIM * C_VEC)   // float4 elems per fmap row

__device__ __forceinline__ int bin_size(int L) {
    int xup = (L + OUT_H - 1) / OUT_H;            // ceil(L/7)
    int m = (xup * (OUT_H - 1) >= L) ? (xup - 1) : xup;
    return m > 1 ? m : 1;
}

__device__ __forceinline__ void fold(float4& a, const float4 v) {
    a.x = fmaxf(a.x, v.x);
    a.y = fmaxf(a.y, v.y);
    a.z = fmaxf(a.z, v.z);
    a.w = fmaxf(a.w, v.w);
}

// One half-block: ty=0 handles bins [0,JS), ty=1 handles [JS,7).
// Bins 0..5 have compile-time width MW; bin 6 (second half only) has
// dynamic width wl in [1,6], loads predicated on k < wl.
template<int MW, bool FIRST>
__device__ __forceinline__ void run_half(const float4* __restrict__ fp,
                                         int cnt, int wl,
                                         float4* __restrict__ obase)
{
    // Balance expected loads: JS ~= round((6*MW + 3.5) / (2*MW))
    constexpr int JS = (14 * MW + 7) / (4 * MW);   // MW=1..5 -> 5,4,4,3,3
    constexpr int J0 = FIRST ? 0 : JS;
    constexpr int J1 = FIRST ? JS : OUT_W;
    constexpr int NB = J1 - J0;

    const float NEG = __int_as_float(0xff800000);   // -inf
    float4 acc[NB];
#pragma unroll
    for (int j = 0; j < NB; ++j)
        acc[j] = make_float4(NEG, NEG, NEG, NEG);

    for (int y = 0; y < cnt; ++y) {
        const float4* row = fp;
        fp += ROW_STRIDE;
#pragma unroll
        for (int j = J0; j < (FIRST ? J1 : OUT_W - 1); ++j) {
#pragma unroll
            for (int k = 0; k < MW; ++k)
                fold(acc[j - J0], __ldg(row + (j * MW + k) * C_VEC));
        }
        if (!FIRST) {
            const float4* rowt = row + (OUT_W - 1) * MW * C_VEC;
#pragma unroll
            for (int k = 0; k < 6; ++k) {
                if (k < wl)
                    fold(acc[NB - 1], __ldg(rowt + k * C_VEC));
            }
        }
    }

#pragma unroll
    for (int j = J0; j < J1; ++j)
        obase[(size_t)j * C_VEC] = acc[j - J0];
}

__global__ __launch_bounds__(128, 8)
void roi_pool_kernel(const float4* __restrict__ fmap,   // [128,128,64] float4
                     const float4* __restrict__ rois,   // [R] (l,r,t,b)
                     float4* __restrict__ out)          // [R,7,7,64] float4
{
    const int r   = blockIdx.x;       // ROI index
    const int i   = blockIdx.y;       // output row 0..6
    const int tid = threadIdx.x;      // 0..63 channel-group
    const bool first = (threadIdx.y == 0);

    const float4 e = rois[r];
    const int l  = __float2int_rn(128.0f * e.x);
    const int rr = __float2int_rn(128.0f * e.y);
    const int t  = __float2int_rn(128.0f * e.z);
    const int b  = __float2int_rn(128.0f * e.w);

    int Lh = b - t; Lh = Lh < OUT_H ? OUT_H : (Lh > 32 ? 32 : Lh);
    int Lw = rr - l; Lw = Lw < OUT_W ? OUT_W : (Lw > 32 ? 32 : Lw);

    const int mh = bin_size(Lh);
    const int mw = bin_size(Lw);
    const int wl = Lw - (OUT_W - 1) * mw;          // last-bin width, 1..6

    const int y0 = i * mh;
    int y1 = (i == OUT_H - 1) ? Lh : (i + 1) * mh;
    if (y1 > Lh) y1 = Lh;
    const int cnt = y1 - y0;                       // 1..6

    const float4* fp = fmap + ((size_t)(t + y0) * W_DIM + l) * C_VEC + tid;
    float4* obase = out + ((size_t)r * OUT_H + i) * OUT_W * C_VEC + tid;

    switch (mw) {
        case 1:
            if (first) run_half<1, true >(fp, cnt, wl, obase);
            else       run_half<1, false>(fp, cnt, wl, obase);
            break;
        case 2:
            if (first) run_half<2, true >(fp, cnt, wl, obase);
            else       run_half<2, false>(fp, cnt, wl, obase);
            break;
        case 3:
            if (first) run_half<3, true >(fp, cnt, wl, obase);
            else       run_half<3, false>(fp, cnt, wl, obase);
            break;
        case 4:
            if (first) run_half<4, true >(fp, cnt, wl, obase);
            else       run_half<4, false>(fp, cnt, wl, obase);
            break;
        default:
            if (first) run_half<5, true >(fp, cnt, wl, obase);
            else       run_half<5, false>(fp, cnt, wl, obase);
            break;
    }
}

extern "C" void kernel_launch(void* const* d_in, const int* in_sizes, int n_in,
                              void* d_out, int out_size)
{
    const float4* fmap = (const float4*)d_in[0];   // [1,128,128,256] f32
    const float4* rois = (const float4*)d_in[1];   // [R,4] f32
    float4* out = (float4*)d_out;

    const int R = in_sizes[1] / 4;

    dim3 grid(R, OUT_H);
    dim3 block(C_VEC, 2);
    roi_pool_kernel<<<grid, block>>>(fmap, rois, out);
}